// round 1
// baseline (speedup 1.0000x reference)
#include <cuda_runtime.h>

#define S3 0.86602540378443864676f   // sqrt(3)/2

// ---------------- scratch (no allocation allowed) ----------------
__device__ float2 g_A[8*32*16*3*128];   // [bi][kx][p][t]   x-DFT output
__device__ float2 g_X[1024*256];        // [mode][b*32+i]   forward modes
__device__ float2 g_W[1024*1024];       // [mode][i*32+o]   transposed weights
__device__ float2 g_Y[8*32*16*32*2];    // [bo][kx][kt][kz] mixed modes
__device__ float2 g_V[8*32*128*16*3];   // [bo][t][kx][p]   t-expanded

// ---------------- k0: weight transpose -> per-mode [i][o] complex ----------
__global__ void k0_wt(const float* __restrict__ w1re, const float* __restrict__ w1im,
                      const float* __restrict__ w2re, const float* __restrict__ w2im) {
    int mode = blockIdx.x;                 // ((kt*16)+kx)*2+kz
    int kz = mode & 1, kx = (mode >> 1) & 15, kt = mode >> 5;
    const float* wre; const float* wim; int ktw;
    if (kt < 16) { wre = w1re; wim = w1im; ktw = kt; }
    else         { wre = w2re; wim = w2im; ktw = kt - 16; }
    for (int r = threadIdx.x; r < 1024; r += 256) {
        int i = r >> 5, o = r & 31;
        int src = (((i*32 + o)*16 + ktw)*16 + kx)*3 + kz;
        g_W[mode*1024 + r] = make_float2(wre[src], wim[src]);
    }
}

// ---------------- k1: x-DFT (256 -> 16 modes), real input -----------------
// block = one (b,i, t-pair); 96 threads: tl(2) x kx(16) x p(3)
__global__ void k1_xdft(const float* __restrict__ x) {
    __shared__ float  xs[1536];
    __shared__ float2 tab[256];
    int blk = blockIdx.x, tid = threadIdx.x;
    int bi = blk >> 6, tp = blk & 63;
    const float* src = x + (size_t)(bi*128 + tp*2) * 768;
    for (int i = tid; i < 1536; i += 96) xs[i] = src[i];
    for (int j = tid; j < 256; j += 96) {
        float s, c; sincospif(j * (1.0f/128.0f), &s, &c);
        tab[j] = make_float2(c, s);
    }
    __syncthreads();
    int tl = tid / 48, r = tid % 48;
    int kx = r & 15, p = r >> 4;
    const float* row = xs + tl*768 + p;
    float re = 0.f, im = 0.f;
    int j = 0;
    #pragma unroll 8
    for (int xi = 0; xi < 256; xi++) {
        float v = row[xi*3];
        float2 cs = tab[j];
        re += v * cs.x;          // e^{-i theta}: re = sum x*cos
        im -= v * cs.y;          //              im = -sum x*sin
        j = (j + kx) & 255;
    }
    g_A[((bi*16 + kx)*3 + p)*128 + (tp*2 + tl)] = make_float2(re, im);
}

// ---------------- k2: t-DFT (128 -> 32 modes) + p-rfft (3 -> 2) -----------
// block = (b,i,kx); 96 threads: kt(32) x p(3)
__global__ void k2_tdft() {
    __shared__ float2 As[384];
    __shared__ float2 tab[128];
    __shared__ float2 Xt[32][3];
    int blk = blockIdx.x, tid = threadIdx.x;
    int bi = blk >> 4, kx = blk & 15;
    const float2* src = g_A + (size_t)(bi*16 + kx)*384;
    for (int i = tid; i < 384; i += 96) As[i] = src[i];
    for (int j = tid; j < 128; j += 96) {
        float s, c; sincospif(j * (1.0f/64.0f), &s, &c);
        tab[j] = make_float2(c, s);
    }
    __syncthreads();
    int kt = tid & 31, p = tid >> 5;
    int ktg = kt + (kt >= 16 ? 96 : 0);    // global mode 0..15 / 112..127
    float re = 0.f, im = 0.f;
    int j = 0;
    #pragma unroll 8
    for (int t = 0; t < 128; t++) {
        float2 a = As[p*128 + t];
        float2 cs = tab[j];
        re += a.x*cs.x + a.y*cs.y;   // (a)(c - i s)
        im += a.y*cs.x - a.x*cs.y;
        j = (j + ktg) & 127;
    }
    Xt[kt][p] = make_float2(re, im);
    __syncthreads();
    if (tid < 64) {
        int kt2 = tid & 31, kz = tid >> 5;
        float2 a0 = Xt[kt2][0], a1 = Xt[kt2][1], a2 = Xt[kt2][2];
        float2 rr;
        if (kz == 0) rr = make_float2(a0.x + a1.x + a2.x, a0.y + a1.y + a2.y);
        else rr = make_float2(a0.x - 0.5f*(a1.x + a2.x) + S3*(a1.y - a2.y),
                              a0.y - 0.5f*(a1.y + a2.y) - S3*(a1.x - a2.x));
        g_X[((kt2*16 + kx)*2 + kz)*256 + bi] = rr;
    }
}

// ---------------- k3: per-mode complex GEMM Y[b,o] = sum_i X[b,i] W[i,o] --
__global__ void k3_mix() {
    __shared__ float2 Xs[256];
    __shared__ float2 Ws[1024];
    int mode = blockIdx.x, tid = threadIdx.x;
    Xs[tid] = g_X[mode*256 + tid];
    #pragma unroll
    for (int k = 0; k < 4; k++) Ws[tid + k*256] = g_W[(size_t)mode*1024 + tid + k*256];
    __syncthreads();
    int b = tid >> 5, o = tid & 31;
    float re = 0.f, im = 0.f;
    #pragma unroll
    for (int i = 0; i < 32; i++) {
        float2 xv = Xs[b*32 + i];
        float2 wv = Ws[i*32 + o];
        re += xv.x*wv.x - xv.y*wv.y;
        im += xv.x*wv.y + xv.y*wv.x;
    }
    int kz = mode & 1, kx = (mode >> 1) & 15, kt = mode >> 5;
    g_Y[(((b*32 + o)*16 + kx)*32 + kt)*2 + kz] = make_float2(re, im);
}

// ---------------- k4: build U_p, expand kt -> t (32 -> 128) ---------------
// block = (bo, kx); 384 threads: t(128) x p(3)
__global__ void k4_texp() {
    __shared__ float2 Ys[64];
    __shared__ float2 U[96];      // [kt*3+p]
    __shared__ float2 tab[128];
    int blk = blockIdx.x, tid = threadIdx.x;
    int bo = blk >> 4, kx = blk & 15;
    if (tid < 64) Ys[tid] = g_Y[(bo*16 + kx)*64 + tid];
    if (tid >= 256) {
        int j = tid - 256;
        float s, c; sincospif(j * (1.0f/64.0f), &s, &c);
        tab[j] = make_float2(c, s);
    }
    __syncthreads();
    if (tid < 96) {
        int kt = tid & 31, p = tid >> 5;
        float2 y0 = Ys[kt*2], y1 = Ys[kt*2 + 1];
        float wx, wy;                         // 2 * e^{2 pi i p / 3}
        if (p == 0)      { wx = 2.f;  wy = 0.f; }
        else if (p == 1) { wx = -1.f; wy =  2.f*S3; }
        else             { wx = -1.f; wy = -2.f*S3; }
        const float SC = 1.f/98304.f;         // 1/(128*256*3)
        U[kt*3 + p] = make_float2(SC*(y0.x + wx*y1.x - wy*y1.y),
                                  SC*(y0.y + wx*y1.y + wy*y1.x));
    }
    __syncthreads();
    int t = tid & 127, p = tid >> 7;
    float re = 0.f, im = 0.f;
    int j = 0;
    #pragma unroll
    for (int kt = 0; kt < 16; kt++) {         // global modes kt
        float2 u = U[kt*3 + p]; float2 cs = tab[j];
        re += u.x*cs.x - u.y*cs.y;            // (u)(c + i s)
        im += u.x*cs.y + u.y*cs.x;
        j = (j + t) & 127;
    }
    j = (112 * t) & 127;                       // global modes 112..127
    #pragma unroll
    for (int kt = 16; kt < 32; kt++) {
        float2 u = U[kt*3 + p]; float2 cs = tab[j];
        re += u.x*cs.x - u.y*cs.y;
        im += u.x*cs.y + u.y*cs.x;
        j = (j + t) & 127;
    }
    g_V[((bo*128 + t)*16 + kx)*3 + p] = make_float2(re, im);
}

// ---------------- k5: expand kx -> x (16 -> 256), take Re, store ----------
// block = (bo, t); 256 threads = x
__global__ void k5_xexp(float* __restrict__ out) {
    __shared__ float2 Vs[48];
    __shared__ float2 tab[256];
    int blk = blockIdx.x, tid = threadIdx.x;
    if (tid < 48) Vs[tid] = g_V[(size_t)blk*48 + tid];
    {
        float s, c; sincospif(tid * (1.0f/128.0f), &s, &c);
        tab[tid] = make_float2(c, s);
    }
    __syncthreads();
    int x = tid;
    float a0 = 0.f, a1 = 0.f, a2 = 0.f;
    int j = 0;
    #pragma unroll
    for (int kx = 0; kx < 16; kx++) {
        float2 cs = tab[j];
        float2 v0 = Vs[kx*3], v1 = Vs[kx*3+1], v2 = Vs[kx*3+2];
        a0 += v0.x*cs.x - v0.y*cs.y;   // Re( V * e^{+i theta} )
        a1 += v1.x*cs.x - v1.y*cs.y;
        a2 += v2.x*cs.x - v2.y*cs.y;
        j = (j + x) & 255;
    }
    float* dst = out + (size_t)blk*768 + x*3;
    dst[0] = a0; dst[1] = a1; dst[2] = a2;
}

extern "C" void kernel_launch(void* const* d_in, const int* in_sizes, int n_in,
                              void* d_out, int out_size) {
    const float* x    = (const float*)d_in[0];
    const float* w1re = (const float*)d_in[1];
    const float* w1im = (const float*)d_in[2];
    const float* w2re = (const float*)d_in[3];
    const float* w2im = (const float*)d_in[4];
    float* out = (float*)d_out;

    k0_wt <<<1024,  256>>>(w1re, w1im, w2re, w2im);
    k1_xdft<<<16384, 96>>>(x);
    k2_tdft<<<4096,  96>>>();
    k3_mix <<<1024,  256>>>();
    k4_texp<<<4096,  384>>>();
    k5_xexp<<<32768, 256>>>(out);
}